// round 6
// baseline (speedup 1.0000x reference)
#include <cuda_runtime.h>
#include <math.h>

#define NB 2
#define NT 512
#define NC 263
#define ND 512
#define NF 257
#define NK 51
#define WINW 24

// output layout (concatenated, float32): out_t | tidx | out_f | fidx
#define OUT_T_OFF 0
#define TIDX_OFF  (NB*NT*ND)                 // 524288
#define OUTF_OFF  (TIDX_OFF + NB*NK)         // 524390
#define FIDX_OFF  (OUTF_OFF + NB*NT*NC)      // 793702

// ---------------- scratch (device globals; no allocation allowed) ----------
__device__ float g_ex [NB*NT*ND];
__device__ float g_h  [NB*NT*ND];
__device__ float g_mtd[NB*NT*ND];
__device__ float g_cre[NB*NF*ND];
__device__ float g_cim[NB*NF*ND];
__device__ float g_score [NB*NT];
__device__ float g_magsum[NB*NF];
__device__ int   g_tidx[NB*NK];
__device__ int   g_fidx[NB*NK];
__device__ unsigned char g_tmask[NB*NT];
__device__ unsigned char g_fmask[NB*NF];
__device__ unsigned char g_tm   [NB*NT];

__device__ __forceinline__ float gelu_f(float x) {
    return 0.5f * x * (1.f + erff(x * 0.7071067811865476f));
}
__device__ __forceinline__ float sigm_f(float x) {
    return 1.f / (1.f + expf(-x));
}

// ---------------- init: zero masks -----------------------------------------
__global__ void init_k() {
    int i = threadIdx.x;
    for (int j = i; j < NB*NF; j += blockDim.x) { g_fmask[j] = 0; }
    for (int j = i; j < NB*NT; j += blockDim.x) { g_tmask[j] = 0; }
}

// ---------------- generic tiled NT/NN SGEMM with fused epilogues -----------
// 64x64 block tile, KT=32 k-tile, 256 threads, 4x4 thread tile.
// EPI 0: ex   = A(x) @ W_emb^T + b_emb + PE          -> g_ex
// EPI 1: h    = gelu(g_ex @ tW1^T + tb1)             -> g_h
// EPI 2: out_t= tmask? t_token : sigmoid(g_h@tW2^T+tb2) -> d_out
// EPI 3: out_f= tm? mx : scalarMLP(mx)   (mx = g_mtd @ W_emb) -> d_out+OUTF
// BLAY 0: B is [N][K] row-major (dot of rows).  BLAY 1: B is [K][N].
#define KT 32
template<int EPI, int BLAY>
__global__ void __launch_bounds__(256)
gemm_k(const float* __restrict__ A, const float* __restrict__ B,
       int M, int N, int K, int lda, int ldb,
       const float* __restrict__ bias,
       const float* __restrict__ aux0,
       const float* __restrict__ aux1,
       const float* __restrict__ aux2,
       const float* __restrict__ fb2p,
       float* __restrict__ Cout, int ldo)
{
    __shared__ __align__(16) float As[KT][72];
    __shared__ __align__(16) float Bs[KT][72];

    const float* Ap = (EPI == 0) ? A : (EPI == 1) ? g_ex : (EPI == 2) ? g_h : g_mtd;

    int tid = threadIdx.x;
    int tx = tid & 15, ty = tid >> 4;
    int m0 = blockIdx.y * 64, n0 = blockIdx.x * 64;

    float acc[4][4] = {};

    for (int k0 = 0; k0 < K; k0 += KT) {
        // A tile 64(m) x 32(k): 8 elements per thread
        {
            int r  = tid >> 2;
            int c8 = (tid & 3) * 8;
            #pragma unroll
            for (int u = 0; u < 8; u++) {
                int k = k0 + c8 + u;
                As[c8 + u][r] = (k < K) ? Ap[(m0 + r) * lda + k] : 0.f;
            }
        }
        if (BLAY == 0) {
            int r  = tid >> 2;
            int c8 = (tid & 3) * 8;
            #pragma unroll
            for (int u = 0; u < 8; u++) {
                int k = k0 + c8 + u;
                int n = n0 + r;
                Bs[c8 + u][r] = (k < K && n < N) ? B[n * ldb + k] : 0.f;
            }
        } else {
            int kk = tid >> 6;      // 0..3
            int nn = tid & 63;
            #pragma unroll
            for (int u = 0; u < 8; u++) {
                int k = k0 + kk + u * 4;
                int n = n0 + nn;
                Bs[kk + u * 4][nn] = (k < K && n < N) ? B[k * ldb + n] : 0.f;
            }
        }
        __syncthreads();
        #pragma unroll
        for (int kk = 0; kk < KT; kk++) {
            float4 av = *(const float4*)&As[kk][ty * 4];
            float4 bv = *(const float4*)&Bs[kk][tx * 4];
            float a[4] = {av.x, av.y, av.z, av.w};
            float b[4] = {bv.x, bv.y, bv.z, bv.w};
            #pragma unroll
            for (int i = 0; i < 4; i++)
                #pragma unroll
                for (int j = 0; j < 4; j++)
                    acc[i][j] += a[i] * b[j];
        }
        __syncthreads();
    }

    #pragma unroll
    for (int i = 0; i < 4; i++) {
        int m = m0 + ty * 4 + i;
        #pragma unroll
        for (int j = 0; j < 4; j++) {
            int n = n0 + tx * 4 + j;
            if (n >= N) continue;
            float v = acc[i][j];
            if (EPI == 0) {
                int t = m & (NT - 1);
                float freq = expf(-(float)(n & ~1) * (9.210340371976184f / 512.0f));
                float ang = (float)t * freq;
                float pe = (n & 1) ? cosf(ang) : sinf(ang);
                g_ex[m * ND + n] = v + bias[n] + pe;
            } else if (EPI == 1) {
                g_h[m * ND + n] = gelu_f(v + bias[n]);
            } else if (EPI == 2) {
                float s = sigm_f(v + bias[n]);
                if (g_tmask[m]) s = aux0[n];          // t_token
                Cout[m * ldo + n] = s;
            } else {
                float o = v;                           // mx value
                if (!g_tm[m]) {
                    float s = 0.f;
                    for (int d = 0; d < ND; d++) {
                        float hv = gelu_f(v * aux0[d] + aux1[d]);  // fW1, fb1
                        s += hv * aux2[d];                          // fW2
                    }
                    o = sigm_f(s + fb2p[0]);
                }
                Cout[m * ldo + n] = o;
            }
        }
    }
}

// ---------------- windowed variance score (shuffle reduction) --------------
__global__ void score_k() {
    int t = blockIdx.x, b = blockIdx.y;
    int tid = threadIdx.x;                 // 256 threads, 2 d each
    int t0 = t - (WINW - 1); if (t0 < 0) t0 = 0;
    float den = (float)((t + 1 < WINW) ? (t + 1) : WINW);
    float vs = 0.f, ms = 0.f;
    #pragma unroll
    for (int h = 0; h < 2; h++) {
        int d = tid + h * 256;
        float s1 = 0.f, s2 = 0.f;
        for (int tt = t0; tt <= t; tt++) {
            float e = g_ex[(b * NT + tt) * ND + d];
            s1 += e; s2 += e * e;
        }
        float m1 = s1 / den;
        vs += s2 / den - m1 * m1;
        ms += m1;
    }
    __shared__ float pv[8], pm[8];
    #pragma unroll
    for (int o = 16; o; o >>= 1) {
        vs += __shfl_down_sync(0xffffffffu, vs, o);
        ms += __shfl_down_sync(0xffffffffu, ms, o);
    }
    if ((tid & 31) == 0) { pv[tid >> 5] = vs; pm[tid >> 5] = ms; }
    __syncthreads();
    if (tid < 32) {
        float v2 = (tid < 8) ? pv[tid] : 0.f;
        float m2 = (tid < 8) ? pm[tid] : 0.f;
        #pragma unroll
        for (int o = 4; o; o >>= 1) {
            v2 += __shfl_down_sync(0xffffffffu, v2, o);
            m2 += __shfl_down_sync(0xffffffffu, m2, o);
        }
        if (tid == 0) g_score[b * NT + t] = v2 / (m2 + 1e-6f);
    }
}

// ---------------- top-k: register-resident iterative argmax ----------------
__global__ void topk_k(int which, float* __restrict__ fout) {
    int b = blockIdx.x;
    const float* vals = which ? g_magsum : g_score;
    int n = which ? NF : NT;
    int* idxo = which ? g_fidx : g_tidx;
    unsigned char* mask = which ? g_fmask : g_tmask;
    int mstride = which ? NF : NT;

    __shared__ float swv[16];
    __shared__ int   swi[16];
    __shared__ int   winner;

    int tid = threadIdx.x;
    const float NEGINF = -__int_as_float(0x7f800000);
    float myv = (tid < n) ? vals[b * n + tid] : NEGINF;

    for (int it = 0; it < NK; it++) {
        float v = myv;
        int   i = tid;
        #pragma unroll
        for (int o = 16; o; o >>= 1) {
            float ov = __shfl_down_sync(0xffffffffu, v, o);
            int   oi = __shfl_down_sync(0xffffffffu, i, o);
            if (ov > v || (ov == v && oi < i)) { v = ov; i = oi; }
        }
        if ((tid & 31) == 0) { swv[tid >> 5] = v; swi[tid >> 5] = i; }
        __syncthreads();
        if (tid < 32) {
            float v2 = (tid < 16) ? swv[tid] : NEGINF;
            int   i2 = (tid < 16) ? swi[tid] : 0x7fffffff;
            #pragma unroll
            for (int o = 8; o; o >>= 1) {
                float ov = __shfl_down_sync(0xffffffffu, v2, o);
                int   oi = __shfl_down_sync(0xffffffffu, i2, o);
                if (ov > v2 || (ov == v2 && oi < i2)) { v2 = ov; i2 = oi; }
            }
            if (tid == 0) {
                winner = i2;
                idxo[b * NK + it] = i2;
                mask[b * mstride + i2] = 1;
                fout[b * NK + it] = (float)i2;
            }
        }
        __syncthreads();
        if (tid == winner) myv = NEGINF;
    }
}

// ---------------- forward DFT (rfft), float2 over d ------------------------
// 256 threads each own d-pair (2*tid, 2*tid+1); FCH=4 freqs per block for
// chip occupancy (grid 65x2 = 130 blocks).
#define FCH 4
__global__ void __launch_bounds__(256) dft_k() {
    __shared__ float ct[512], st[512];
    for (int k = threadIdx.x; k < 512; k += blockDim.x) {
        float s, c;
        sincospif((float)k / 256.f, &s, &c);
        ct[k] = c; st[k] = s;
    }
    __syncthreads();
    int b  = blockIdx.y;
    int f0 = blockIdx.x * FCH;
    int d  = threadIdx.x * 2;

    float2 re[FCH], im[FCH];
    int iu[FCH];
    #pragma unroll
    for (int u = 0; u < FCH; u++) {
        re[u] = make_float2(0.f, 0.f);
        im[u] = make_float2(0.f, 0.f);
        iu[u] = 0;
    }

    const float* exp_ = g_ex + (size_t)(b * NT) * ND + d;
    for (int t = 0; t < NT; t++) {
        float2 e = *(const float2*)&exp_[(size_t)t * ND];
        #pragma unroll
        for (int u = 0; u < FCH; u++) {
            float c = ct[iu[u]], s = st[iu[u]];
            re[u].x += e.x * c;  re[u].y += e.y * c;
            im[u].x -= e.x * s;  im[u].y -= e.y * s;
            iu[u] = (iu[u] + f0 + u) & 511;
        }
    }
    #pragma unroll
    for (int u = 0; u < FCH; u++) {
        int f = f0 + u;
        if (f < NF) {
            *(float2*)&g_cre[(b * NF + f) * ND + d] = re[u];
            *(float2*)&g_cim[(b * NF + f) * ND + d] = im[u];
        }
    }
}

// ---------------- deterministic magnitude reduction over D -----------------
__global__ void mag_k() {
    int f = blockIdx.x, b = blockIdx.y;
    int tid = threadIdx.x;                 // 256 threads, 2 d each
    float s = 0.f;
    #pragma unroll
    for (int h = 0; h < 2; h++) {
        int d = tid + h * 256;
        float re = g_cre[(b * NF + f) * ND + d];
        float im = g_cim[(b * NF + f) * ND + d];
        s += sqrtf(re * re + im * im);
    }
    __shared__ float sh[256];
    sh[tid] = s;
    __syncthreads();
    for (int o = 128; o > 0; o >>= 1) {
        if (tid < o) sh[tid] += sh[tid + o];
        __syncthreads();
    }
    if (tid == 0) g_magsum[b * NF + f] = sh[0];
}

// ---------------- time-domain mask of irfft(fmask) != 0 --------------------
__global__ void tm_k() {
    int b = blockIdx.x, t = threadIdx.x;
    double v = 0.0;
    for (int i = 0; i < NK; i++) {
        int f = g_fidx[b * NK + i];
        double w = (f == 0 || f == 256) ? 1.0 : 2.0;
        v += w * cospi((double)((f * t) & 511) / 256.0);
    }
    g_tm[b * NT + t] = (v != 0.0) ? 1 : 0;
}

// ---------------- inverse DFT (irfft of masked spectrum), float2 over d ----
#define TCH 8
__global__ void __launch_bounds__(256) idft_k(const float* __restrict__ tokre,
                                              const float* __restrict__ tokim) {
    __shared__ float ct[512], st[512];
    __shared__ unsigned char fm[NF];
    int b = blockIdx.y;
    for (int k = threadIdx.x; k < 512; k += blockDim.x) {
        float s, c;
        sincospif((float)k / 256.f, &s, &c);
        ct[k] = c; st[k] = s;
    }
    for (int k = threadIdx.x; k < NF; k += blockDim.x) fm[k] = g_fmask[b * NF + k];
    __syncthreads();

    int t0 = blockIdx.x * TCH;
    int d  = threadIdx.x * 2;

    float2 acc[TCH];
    int ju[TCH];
    #pragma unroll
    for (int u = 0; u < TCH; u++) { acc[u] = make_float2(0.f, 0.f); ju[u] = 0; }
    float2 tre = *(const float2*)&tokre[d];
    float2 tim = *(const float2*)&tokim[d];

    for (int f = 0; f < NF; f++) {
        float2 re, im;
        if (fm[f]) { re = tre; im = tim; }
        else {
            re = *(const float2*)&g_cre[(b * NF + f) * ND + d];
            im = *(const float2*)&g_cim[(b * NF + f) * ND + d];
        }
        float w = (f == 0 || f == 256) ? 1.f : 2.f;
        re.x *= w; re.y *= w; im.x *= w; im.y *= w;
        #pragma unroll
        for (int u = 0; u < TCH; u++) {
            float c = ct[ju[u]], s = st[ju[u]];
            acc[u].x += re.x * c - im.x * s;
            acc[u].y += re.y * c - im.y * s;
            ju[u] = (ju[u] + t0 + u) & 511;
        }
    }
    #pragma unroll
    for (int u = 0; u < TCH; u++) {
        float2 o = make_float2(acc[u].x * (1.f / 512.f), acc[u].y * (1.f / 512.f));
        *(float2*)&g_mtd[(b * NT + t0 + u) * ND + d] = o;
    }
}

// ---------------- launch ----------------------------------------------------
extern "C" void kernel_launch(void* const* d_in, const int* in_sizes, int n_in,
                              void* d_out, int out_size) {
    const float* x       = (const float*)d_in[0];
    const float* W_emb   = (const float*)d_in[1];
    const float* b_emb   = (const float*)d_in[2];
    const float* t_token = (const float*)d_in[3];
    const float* tW1     = (const float*)d_in[4];
    const float* tb1     = (const float*)d_in[5];
    const float* tW2     = (const float*)d_in[6];
    const float* tb2     = (const float*)d_in[7];
    const float* f_re    = (const float*)d_in[8];
    const float* f_im    = (const float*)d_in[9];
    const float* fW1     = (const float*)d_in[10];
    const float* fb1     = (const float*)d_in[11];
    const float* fW2     = (const float*)d_in[12];
    const float* fb2     = (const float*)d_in[13];
    float* out = (float*)d_out;

    init_k<<<1, 512>>>();

    // ex = x @ W_emb^T + b_emb + PE
    {
        dim3 g(ND / 64, (NB * NT) / 64);
        gemm_k<0, 0><<<g, 256>>>(x, W_emb, NB * NT, ND, NC, NC, NC,
                                 b_emb, nullptr, nullptr, nullptr, nullptr,
                                 nullptr, 0);
    }
    // windowed variance score + temporal topk
    {
        dim3 g(NT, NB);
        score_k<<<g, 256>>>();
        topk_k<<<NB, 512>>>(0, out + TIDX_OFF);
    }
    // h = gelu(ex @ tW1^T + tb1)
    {
        dim3 g(ND / 64, (NB * NT) / 64);
        gemm_k<1, 0><<<g, 256>>>(nullptr, tW1, NB * NT, ND, ND, ND, ND,
                                 tb1, nullptr, nullptr, nullptr, nullptr,
                                 nullptr, 0);
        // out_t = tmask ? t_token : sigmoid(h @ tW2^T + tb2)
        gemm_k<2, 0><<<g, 256>>>(nullptr, tW2, NB * NT, ND, ND, ND, ND,
                                 tb2, t_token, nullptr, nullptr, nullptr,
                                 out + OUT_T_OFF, ND);
    }
    // rfft + deterministic magnitude mean + freq topk
    {
        dim3 g((NF + FCH - 1) / FCH, NB, 1);
        dft_k<<<g, 256>>>();
        dim3 gm(NF, NB);
        mag_k<<<gm, 256>>>();
        topk_k<<<NB, 512>>>(1, out + FIDX_OFF);
        tm_k<<<NB, NT>>>();
    }
    // irfft of masked spectrum
    {
        dim3 g(NT / TCH, NB, 1);
        idft_k<<<g, 256>>>(f_re, f_im);
    }
    // out_f = tm ? (mtd @ W_emb) : scalarMLP(...)
    {
        dim3 g((NC + 63) / 64, (NB * NT) / 64);
        gemm_k<3, 1><<<g, 256>>>(nullptr, W_emb, NB * NT, NC, ND, ND, NC,
                                 nullptr, fW1, fb1, fW2, fb2,
                                 out + OUTF_OFF, NC);
    }
}

// round 11
// speedup vs baseline: 1.5274x; 1.5274x over previous
#include <cuda_runtime.h>
#include <math.h>

#define NB 2
#define NT 512
#define NC 263
#define ND 512
#define NF 257
#define NK 51
#define WINW 24

// output layout (concatenated, float32): out_t | tidx | out_f | fidx
#define OUT_T_OFF 0
#define TIDX_OFF  (NB*NT*ND)                 // 524288
#define OUTF_OFF  (TIDX_OFF + NB*NK)         // 524390
#define FIDX_OFF  (OUTF_OFF + NB*NT*NC)      // 793702

// ---------------- scratch (device globals; no allocation allowed) ----------
__device__ float g_ex [NB*NT*ND];
__device__ float g_h  [NB*NT*ND];
__device__ float g_mtd[NB*NT*ND];
__device__ float g_cre[NB*NF*ND];
__device__ float g_cim[NB*NF*ND];
__device__ float g_score [NB*NT];
__device__ float g_magsum[NB*NF];
__device__ int   g_tidx[NB*NK];
__device__ int   g_fidx[NB*NK];
__device__ unsigned char g_tmask[NB*NT];
__device__ unsigned char g_fmask[NB*NF];
__device__ unsigned char g_tm   [NB*NT];

__device__ __forceinline__ float gelu_f(float x) {
    return 0.5f * x * (1.f + erff(x * 0.7071067811865476f));
}
__device__ __forceinline__ float sigm_f(float x) {
    return 1.f / (1.f + expf(-x));
}

// ---- packed f32x2 helpers (sm_103a; per-lane IEEE fp32 FMA) ---------------
typedef unsigned long long u64;
__device__ __forceinline__ u64 pk2(float lo, float hi) {
    u64 r; asm("mov.b64 %0, {%1, %2};" : "=l"(r) : "f"(lo), "f"(hi)); return r;
}
__device__ __forceinline__ float2 upk2(u64 v) {
    float2 r; asm("mov.b64 {%0, %1}, %2;" : "=f"(r.x), "=f"(r.y) : "l"(v)); return r;
}
__device__ __forceinline__ u64 fma2(u64 a, u64 b, u64 c) {
    u64 d; asm("fma.rn.f32x2 %0, %1, %2, %3;" : "=l"(d) : "l"(a), "l"(b), "l"(c)); return d;
}
__device__ __forceinline__ u64 mul2(u64 a, u64 b) {
    u64 d; asm("mul.rn.f32x2 %0, %1, %2;" : "=l"(d) : "l"(a), "l"(b)); return d;
}

// ---------------- init: zero masks -----------------------------------------
__global__ void init_k() {
    int i = threadIdx.x;
    for (int j = i; j < NB*NF; j += blockDim.x) { g_fmask[j] = 0; }
    for (int j = i; j < NB*NT; j += blockDim.x) { g_tmask[j] = 0; }
}

// ---------------- double-buffered tiled SGEMM with fused epilogues ---------
// 64x64 block tile, KT=32 k-tile, 256 threads, 4x4 thread tile.
// Inner loop uses packed fma.rn.f32x2 (Blackwell dual-rate FP32): per kk,
// 2 free b-pair packs (float4 regs adjacent) + 4 a-splats + 8 FFMA2
// replaces 16 scalar FFMA. Per-lane IEEE fp32 -> bit-identical results.
#define KT 32
template<int EPI, int BLAY>
__global__ void __launch_bounds__(256)
gemm_k(const float* __restrict__ A, const float* __restrict__ B,
       int M, int N, int K, int lda, int ldb,
       const float* __restrict__ bias,
       const float* __restrict__ aux0,
       const float* __restrict__ aux1,
       const float* __restrict__ aux2,
       const float* __restrict__ fb2p,
       float* __restrict__ Cout, int ldo)
{
    __shared__ __align__(16) float As[2][KT][72];
    __shared__ __align__(16) float Bs[2][KT][72];

    const float* Ap = (EPI == 0) ? A : (EPI == 1) ? g_ex : (EPI == 2) ? g_h : g_mtd;

    int tid = threadIdx.x;
    int tx = tid & 15, ty = tid >> 4;
    int m0 = blockIdx.y * 64, n0 = blockIdx.x * 64;

    int sr  = tid >> 2;          // 0..63 (row for A / BLAY0 B)
    int sc8 = (tid & 3) * 8;     // k-offset base
    int skk = tid >> 6;          // 0..3  (BLAY1)
    int snn = tid & 63;          // 0..63 (BLAY1)

    float ra[8], rb[8];

    #pragma unroll
    for (int u = 0; u < 8; u++) {
        int k = sc8 + u;
        ra[u] = (k < K) ? Ap[(m0 + sr) * lda + k] : 0.f;
    }
    if (BLAY == 0) {
        #pragma unroll
        for (int u = 0; u < 8; u++) {
            int k = sc8 + u;
            int n = n0 + sr;
            rb[u] = (k < K && n < N) ? B[n * ldb + k] : 0.f;
        }
    } else {
        #pragma unroll
        for (int u = 0; u < 8; u++) {
            int k = skk + u * 4;
            int n = n0 + snn;
            rb[u] = (k < K && n < N) ? B[k * ldb + n] : 0.f;
        }
    }
    #pragma unroll
    for (int u = 0; u < 8; u++) As[0][sc8 + u][sr] = ra[u];
    if (BLAY == 0) {
        #pragma unroll
        for (int u = 0; u < 8; u++) Bs[0][sc8 + u][sr] = rb[u];
    } else {
        #pragma unroll
        for (int u = 0; u < 8; u++) Bs[0][skk + u * 4][snn] = rb[u];
    }
    __syncthreads();

    u64 acc2[4][2] = {};
    int cur = 0;

    for (int k0 = 0; k0 < K; k0 += KT) {
        bool has_next = (k0 + KT < K);
        if (has_next) {
            int kb = k0 + KT;
            #pragma unroll
            for (int u = 0; u < 8; u++) {
                int k = kb + sc8 + u;
                ra[u] = (k < K) ? Ap[(m0 + sr) * lda + k] : 0.f;
            }
            if (BLAY == 0) {
                #pragma unroll
                for (int u = 0; u < 8; u++) {
                    int k = kb + sc8 + u;
                    int n = n0 + sr;
                    rb[u] = (k < K && n < N) ? B[n * ldb + k] : 0.f;
                }
            } else {
                #pragma unroll
                for (int u = 0; u < 8; u++) {
                    int k = kb + skk + u * 4;
                    int n = n0 + snn;
                    rb[u] = (k < K && n < N) ? B[k * ldb + n] : 0.f;
                }
            }
        }
        #pragma unroll
        for (int kk = 0; kk < KT; kk++) {
            float4 av = *(const float4*)&As[cur][kk][ty * 4];
            float4 bv = *(const float4*)&Bs[cur][kk][tx * 4];
            u64 b01 = pk2(bv.x, bv.y);
            u64 b23 = pk2(bv.z, bv.w);
            float a[4] = {av.x, av.y, av.z, av.w};
            #pragma unroll
            for (int i = 0; i < 4; i++) {
                u64 a2 = pk2(a[i], a[i]);
                acc2[i][0] = fma2(a2, b01, acc2[i][0]);
                acc2[i][1] = fma2(a2, b23, acc2[i][1]);
            }
        }
        if (has_next) {
            int nxt = cur ^ 1;
            #pragma unroll
            for (int u = 0; u < 8; u++) As[nxt][sc8 + u][sr] = ra[u];
            if (BLAY == 0) {
                #pragma unroll
                for (int u = 0; u < 8; u++) Bs[nxt][sc8 + u][sr] = rb[u];
            } else {
                #pragma unroll
                for (int u = 0; u < 8; u++) Bs[nxt][skk + u * 4][snn] = rb[u];
            }
            __syncthreads();
            cur = nxt;
        }
    }

    // unpack accumulators to scalar 4x4
    float acc[4][4];
    #pragma unroll
    for (int i = 0; i < 4; i++) {
        float2 p0 = upk2(acc2[i][0]);
        float2 p1 = upk2(acc2[i][1]);
        acc[i][0] = p0.x; acc[i][1] = p0.y;
        acc[i][2] = p1.x; acc[i][3] = p1.y;
    }

    #pragma unroll
    for (int i = 0; i < 4; i++) {
        int m = m0 + ty * 4 + i;
        #pragma unroll
        for (int j = 0; j < 4; j++) {
            int n = n0 + tx * 4 + j;
            if (n >= N) continue;
            float v = acc[i][j];
            if (EPI == 0) {
                int t = m & (NT - 1);
                float freq = expf(-(float)(n & ~1) * (9.210340371976184f / 512.0f));
                float ang = (float)t * freq;
                float pe = (n & 1) ? cosf(ang) : sinf(ang);
                g_ex[m * ND + n] = v + bias[n] + pe;
            } else if (EPI == 1) {
                g_h[m * ND + n] = gelu_f(v + bias[n]);
            } else if (EPI == 2) {
                float s = sigm_f(v + bias[n]);
                if (g_tmask[m]) s = aux0[n];          // t_token
                Cout[m * ldo + n] = s;
            } else {
                float o = v;                           // mx value
                if (!g_tm[m]) {
                    float s = 0.f;
                    for (int d = 0; d < ND; d++) {
                        float hv = gelu_f(v * aux0[d] + aux1[d]);  // fW1, fb1
                        s += hv * aux2[d];                          // fW2
                    }
                    o = sigm_f(s + fb2p[0]);
                }
                Cout[m * ldo + n] = o;
            }
        }
    }
}

// ---------------- windowed variance score (shuffle reduction) --------------
__global__ void score_k() {
    int t = blockIdx.x, b = blockIdx.y;
    int tid = threadIdx.x;                 // 256 threads, 2 d each
    int t0 = t - (WINW - 1); if (t0 < 0) t0 = 0;
    float den = (float)((t + 1 < WINW) ? (t + 1) : WINW);
    float vs = 0.f, ms = 0.f;
    #pragma unroll
    for (int h = 0; h < 2; h++) {
        int d = tid + h * 256;
        float s1 = 0.f, s2 = 0.f;
        for (int tt = t0; tt <= t; tt++) {
            float e = g_ex[(b * NT + tt) * ND + d];
            s1 += e; s2 += e * e;
        }
        float m1 = s1 / den;
        vs += s2 / den - m1 * m1;
        ms += m1;
    }
    __shared__ float pv[8], pm[8];
    #pragma unroll
    for (int o = 16; o; o >>= 1) {
        vs += __shfl_down_sync(0xffffffffu, vs, o);
        ms += __shfl_down_sync(0xffffffffu, ms, o);
    }
    if ((tid & 31) == 0) { pv[tid >> 5] = vs; pm[tid >> 5] = ms; }
    __syncthreads();
    if (tid < 32) {
        float v2 = (tid < 8) ? pv[tid] : 0.f;
        float m2 = (tid < 8) ? pm[tid] : 0.f;
        #pragma unroll
        for (int o = 4; o; o >>= 1) {
            v2 += __shfl_down_sync(0xffffffffu, v2, o);
            m2 += __shfl_down_sync(0xffffffffu, m2, o);
        }
        if (tid == 0) g_score[b * NT + t] = v2 / (m2 + 1e-6f);
    }
}

// ---------------- top-k via bitonic sort, both problems in one launch ------
__global__ void __launch_bounds__(512) topk_k(float* __restrict__ out) {
    int b = blockIdx.x, which = blockIdx.y;
    const float* vals = which ? g_magsum : g_score;
    int n = which ? NF : NT;
    int* idxo = which ? g_fidx : g_tidx;
    unsigned char* mask = which ? g_fmask : g_tmask;
    int mstride = which ? NF : NT;
    float* fout = out + (which ? FIDX_OFF : TIDX_OFF);

    __shared__ float sv[512];
    __shared__ int   si[512];
    int tid = threadIdx.x;
    const float NEGINF = -__int_as_float(0x7f800000);
    sv[tid] = (tid < n) ? vals[b * n + tid] : NEGINF;
    si[tid] = tid;
    __syncthreads();

    #pragma unroll 1
    for (int k = 2; k <= 512; k <<= 1) {
        #pragma unroll 1
        for (int j = k >> 1; j > 0; j >>= 1) {
            int ixj = tid ^ j;
            if (ixj > tid) {
                float v1 = sv[tid], v2 = sv[ixj];
                int   i1 = si[tid], i2 = si[ixj];
                bool lt = (v1 < v2) || (v1 == v2 && i1 > i2); // tid-elem "worse"
                bool up = ((tid & k) == 0);
                if (lt == up) {
                    sv[tid] = v2; sv[ixj] = v1;
                    si[tid] = i2; si[ixj] = i1;
                }
            }
            __syncthreads();
        }
    }
    if (tid < NK) {
        int idx = si[tid];
        idxo[b * NK + tid] = idx;
        fout[b * NK + tid] = (float)idx;
        mask[b * mstride + idx] = 1;
    }
}

// ---------------- forward DFT (rfft), packed f32x2 over d-pairs ------------
#define FCH 4
__global__ void __launch_bounds__(256) dft_k() {
    __shared__ u64 ct2[512], st2n[512];
    for (int k = threadIdx.x; k < 512; k += blockDim.x) {
        float s, c;
        sincospif((float)k / 256.f, &s, &c);
        ct2[k]  = pk2(c, c);
        st2n[k] = pk2(-s, -s);
    }
    __syncthreads();
    int b  = blockIdx.y;
    int f0 = blockIdx.x * FCH;
    int d  = threadIdx.x * 2;

    u64 re2[FCH], im2[FCH];
    int iu[FCH];
    #pragma unroll
    for (int u = 0; u < FCH; u++) { re2[u] = 0ull; im2[u] = 0ull; iu[u] = 0; }

    const u64* exp_ = (const u64*)(g_ex + (size_t)(b * NT) * ND + d);
    for (int t = 0; t < NT; t++) {
        u64 e2 = exp_[(size_t)t * (ND / 2)];
        #pragma unroll
        for (int u = 0; u < FCH; u++) {
            re2[u] = fma2(e2, ct2[iu[u]],  re2[u]);
            im2[u] = fma2(e2, st2n[iu[u]], im2[u]);
            iu[u] = (iu[u] + f0 + u) & 511;
        }
    }
    #pragma unroll
    for (int u = 0; u < FCH; u++) {
        int f = f0 + u;
        if (f < NF) {
            *(float2*)&g_cre[(b * NF + f) * ND + d] = upk2(re2[u]);
            *(float2*)&g_cim[(b * NF + f) * ND + d] = upk2(im2[u]);
        }
    }
}

// ---------------- deterministic magnitude reduction over D (shuffle) -------
__global__ void mag_k() {
    int f = blockIdx.x, b = blockIdx.y;
    int tid = threadIdx.x;                 // 256 threads, 2 d each
    float s = 0.f;
    #pragma unroll
    for (int h = 0; h < 2; h++) {
        int d = tid + h * 256;
        float re = g_cre[(b * NF + f) * ND + d];
        float im = g_cim[(b * NF + f) * ND + d];
        s += sqrtf(re * re + im * im);
    }
    __shared__ float ps[8];
    #pragma unroll
    for (int o = 16; o; o >>= 1) s += __shfl_down_sync(0xffffffffu, s, o);
    if ((tid & 31) == 0) ps[tid >> 5] = s;
    __syncthreads();
    if (tid < 32) {
        float v = (tid < 8) ? ps[tid] : 0.f;
        #pragma unroll
        for (int o = 4; o; o >>= 1) v += __shfl_down_sync(0xffffffffu, v, o);
        if (tid == 0) g_magsum[b * NF + f] = v;
    }
}

// ---------------- time-domain mask of irfft(fmask) != 0 --------------------
__global__ void tm_k() {
    __shared__ double ctab[512];
    int b = blockIdx.x, t = threadIdx.x;
    ctab[t] = cospi((double)t / 256.0);
    __syncthreads();
    double v = 0.0;
    for (int i = 0; i < NK; i++) {
        int f = g_fidx[b * NK + i];
        double w = (f == 0 || f == 256) ? 1.0 : 2.0;
        v += w * ctab[(f * t) & 511];
    }
    g_tm[b * NT + t] = (v != 0.0) ? 1 : 0;
}

// ---------------- inverse DFT (irfft of masked spectrum), f32x2 ------------
#define TCH 8
__global__ void __launch_bounds__(256) idft_k(const float* __restrict__ tokre,
                                              const float* __restrict__ tokim) {
    __shared__ u64 ct2[512], st2n[512];
    __shared__ unsigned char fm[NF];
    int b = blockIdx.y;
    for (int k = threadIdx.x; k < 512; k += blockDim.x) {
        float s, c;
        sincospif((float)k / 256.f, &s, &c);
        ct2[k]  = pk2(c, c);
        st2n[k] = pk2(-s, -s);
    }
    for (int k = threadIdx.x; k < NF; k += blockDim.x) fm[k] = g_fmask[b * NF + k];
    __syncthreads();

    int t0 = blockIdx.x * TCH;
    int d  = threadIdx.x * 2;

    u64 acc[TCH];
    int ju[TCH];
    #pragma unroll
    for (int u = 0; u < TCH; u++) { acc[u] = 0ull; ju[u] = 0; }
    u64 tre2 = pk2(tokre[d], tokre[d + 1]);
    u64 tim2 = pk2(tokim[d], tokim[d + 1]);

    const u64 one2 = pk2(1.f, 1.f), two2 = pk2(2.f, 2.f);

    for (int f = 0; f < NF; f++) {
        u64 re2, im2;
        if (fm[f]) { re2 = tre2; im2 = tim2; }
        else {
            re2 = *(const u64*)&g_cre[(b * NF + f) * ND + d];
            im2 = *(const u64*)&g_cim[(b * NF + f) * ND + d];
        }
        u64 w2 = (f == 0 || f == 256) ? one2 : two2;
        re2 = mul2(re2, w2);
        im2 = mul2(im2, w2);
        #pragma unroll
        for (int u = 0; u < TCH; u++) {
            acc[u] = fma2(re2, ct2[ju[u]],  acc[u]);
            acc[u] = fma2(im2, st2n[ju[u]], acc[u]);
            ju[u] = (ju[u] + t0 + u) & 511;
        }
    }
    #pragma unroll
    for (int u = 0; u < TCH; u++) {
        float2 o = upk2(acc[u]);
        o.x *= (1.f / 512.f); o.y *= (1.f / 512.f);
        *(float2*)&g_mtd[(b * NT + t0 + u) * ND + d] = o;
    }
}

// ---------------- launch ----------------------------------------------------
// gemm_k<1,0> kept at launch index 5 so ncu (-s 5 -c 1) profiles the 512^3
// GEMM with the new f32x2 inner loop — measurement and change coincide.
extern "C" void kernel_launch(void* const* d_in, const int* in_sizes, int n_in,
                              void* d_out, int out_size) {
    const float* x       = (const float*)d_in[0];
    const float* W_emb   = (const float*)d_in[1];
    const float* b_emb   = (const float*)d_in[2];
    const float* t_token = (const float*)d_in[3];
    const float* tW1     = (const float*)d_in[4];
    const float* tb1     = (const float*)d_in[5];
    const float* tW2     = (const float*)d_in[6];
    const float* tb2     = (const float*)d_in[7];
    const float* f_re    = (const float*)d_in[8];
    const float* f_im    = (const float*)d_in[9];
    const float* fW1     = (const float*)d_in[10];
    const float* fb1     = (const float*)d_in[11];
    const float* fW2     = (const float*)d_in[12];
    const float* fb2     = (const float*)d_in[13];
    float* out = (float*)d_out;

    // idx 0
    init_k<<<1, 512>>>();

    // idx 1: ex = x @ W_emb^T + b_emb + PE
    {
        dim3 g(ND / 64, (NB * NT) / 64);
        gemm_k<0, 0><<<g, 256>>>(x, W_emb, NB * NT, ND, NC, NC, NC,
                                 b_emb, nullptr, nullptr, nullptr, nullptr,
                                 nullptr, 0);
    }
    // idx 2-4: score, spectrum, magnitudes (all depend only on g_ex)
    {
        dim3 gs(NT, NB);
        score_k<<<gs, 256>>>();
        dim3 gd((NF + FCH - 1) / FCH, NB, 1);
        dft_k<<<gd, 256>>>();
        dim3 gm(NF, NB);
        mag_k<<<gm, 256>>>();
    }
    // idx 5: h = gelu(ex @ tW1^T + tb1)   <-- ncu profiles this launch
    {
        dim3 g(ND / 64, (NB * NT) / 64);
        gemm_k<1, 0><<<g, 256>>>(nullptr, tW1, NB * NT, ND, ND, ND, ND,
                                 tb1, nullptr, nullptr, nullptr, nullptr,
                                 nullptr, 0);
    }
    // idx 6-7: both topk problems in one launch, then time-domain mask
    {
        topk_k<<<dim3(NB, 2), 512>>>(out);
        tm_k<<<NB, NT>>>();
    }
    // idx 8: out_t = tmask ? t_token : sigmoid(h @ tW2^T + tb2)
    {
        dim3 g(ND / 64, (NB * NT) / 64);
        gemm_k<2, 0><<<g, 256>>>(nullptr, tW2, NB * NT, ND, ND, ND, ND,
                                 tb2, t_token, nullptr, nullptr, nullptr,
                                 out + OUT_T_OFF, ND);
    }
    // idx 9: irfft of masked spectrum
    {
        dim3 g(NT / TCH, NB, 1);
        idft_k<<<g, 256>>>(f_re, f_im);
    }
    // idx 10: out_f = tm ? (mtd @ W_emb) : scalarMLP(...)
    {
        dim3 g((NC + 63) / 64, (NB * NT) / 64);
        gemm_k<3, 1><<<g, 256>>>(nullptr, W_emb, NB * NT, NC, ND, ND, NC,
                                 nullptr, fW1, fb1, fW2, fb2,
                                 out + OUTF_OFF, NC);
    }
}

// round 14
// speedup vs baseline: 2.4816x; 1.6247x over previous
#include <cuda_runtime.h>
#include <math.h>

#define NB 2
#define NT 512
#define NC 263
#define ND 512
#define NF 257
#define NK 51
#define WINW 24

// output layout (concatenated, float32): out_t | tidx | out_f | fidx
#define OUT_T_OFF 0
#define TIDX_OFF  (NB*NT*ND)                 // 524288
#define OUTF_OFF  (TIDX_OFF + NB*NK)         // 524390
#define FIDX_OFF  (OUTF_OFF + NB*NT*NC)      // 793702

// DFT-as-GEMM dimensions
#define MF   (2*NF)          // 514 spectrum rows (re stacked over im)
#define MFP  576             // padded twiddle rows (multiple of 64)
#define CS   (MF*ND)         // per-batch spectrum stride

// ---------------- scratch (device globals; no allocation allowed) ----------
__device__ float g_ex [NB*NT*ND];
__device__ float g_h  [NB*NT*ND];
__device__ float g_mtd[NB*NT*ND];
__device__ float g_c  [NB*CS];        // stacked spectrum [re(257) ; im(257)] x d
__device__ float g_cm [NB*CS];        // masked+weighted spectrum for inverse
__device__ float g_wf [MFP*NT];       // forward twiddles [576][512]
__device__ float g_wi [NT*MF];        // inverse twiddles [512][514]
__device__ float g_score [NB*NT];
__device__ float g_magsum[NB*NF];
__device__ int   g_tidx[NB*NK];
__device__ int   g_fidx[NB*NK];
__device__ unsigned char g_tmask[NB*NT];
__device__ unsigned char g_fmask[NB*NF];
__device__ unsigned char g_tm   [NB*NT];

__device__ __forceinline__ float gelu_f(float x) {
    return 0.5f * x * (1.f + erff(x * 0.7071067811865476f));
}
__device__ __forceinline__ float sigm_f(float x) {
    return 1.f / (1.f + expf(-x));
}

// ---- packed f32x2 helpers (sm_103a; per-lane IEEE fp32 FMA) ---------------
typedef unsigned long long u64;
__device__ __forceinline__ u64 pk2(float lo, float hi) {
    u64 r; asm("mov.b64 %0, {%1, %2};" : "=l"(r) : "f"(lo), "f"(hi)); return r;
}
__device__ __forceinline__ float2 upk2(u64 v) {
    float2 r; asm("mov.b64 {%0, %1}, %2;" : "=f"(r.x), "=f"(r.y) : "l"(v)); return r;
}
__device__ __forceinline__ u64 fma2(u64 a, u64 b, u64 c) {
    u64 d; asm("fma.rn.f32x2 %0, %1, %2, %3;" : "=l"(d) : "l"(a), "l"(b), "l"(c)); return d;
}

// ---------------- fused twiddle fill + mask init ---------------------------
// blocks [0, MFP): forward rows g_wf[r][t]; blocks [MFP, MFP+NT): inverse
// rows g_wi[t][f]. Blocks 0/1 additionally zero the top-k masks (consumed
// only several launches later).
__global__ void fill_w_k() {
    int blk = blockIdx.x;
    if (blk == 0) {
        for (int j = threadIdx.x; j < NB*NF; j += blockDim.x) g_fmask[j] = 0;
    } else if (blk == 1) {
        for (int j = threadIdx.x; j < NB*NT; j += blockDim.x) g_tmask[j] = 0;
    }
    if (blk < MFP) {
        int r = blk, t = threadIdx.x;
        float v;
        if (r < NF)      v = cospif((float)((r * t) & 511) / 256.f);
        else if (r < MF) v = -sinpif((float)(((r - NF) * t) & 511) / 256.f);
        else             v = 0.f;
        g_wf[r * NT + t] = v;
    } else {
        int t = blk - MFP;
        for (int f = threadIdx.x; f < MF; f += blockDim.x) {
            float v;
            if (f < NF) v = cospif((float)((f * t) & 511) / 256.f);
            else        v = -sinpif((float)(((f - NF) * t) & 511) / 256.f);
            g_wi[t * MF + f] = v;
        }
    }
}

// ---------------- masked+weighted spectrum prep for inverse ----------------
__global__ void cmprep_k(const float* __restrict__ tokre,
                         const float* __restrict__ tokim) {
    int r = blockIdx.x, b = blockIdx.y, d = threadIdx.x;
    int f = (r < NF) ? r : (r - NF);
    float w = (f == 0 || f == 256) ? 1.f : 2.f;
    float v;
    if (g_fmask[b * NF + f]) v = (r < NF) ? tokre[d] : tokim[d];
    else                     v = g_c[b * CS + r * ND + d];
    g_cm[b * CS + r * ND + d] = w * v;
}

// ---------------- double-buffered tiled SGEMM with fused epilogues ---------
// 64x64 block tile, KT=32 k-tile, 256 threads, 4x4 thread tile, f32x2 FMA.
// EPI 0: ex   = A(x) @ W_emb^T + b_emb + PE            -> g_ex
// EPI 1: h    = gelu(g_ex @ tW1^T + tb1)               -> g_h
// EPI 2: out_t= tmask? t_token : sigmoid(g_h@tW2^T+tb2)-> d_out
// EPI 3: out_f= tm? mx : scalarMLP(mx)                 -> d_out+OUTF
// EPI 4: plain store with m<M guard (forward DFT)      -> g_c
// EPI 5: store v/512 (inverse DFT)                     -> g_mtd
// BLAY 0: B is [N][K]. BLAY 1: B is [K][N].
// blockIdx.z batches B/C via strides bsB/bsC (A shared).
#define KT 32
template<int EPI, int BLAY>
__global__ void __launch_bounds__(256)
gemm_k(const float* __restrict__ A, const float* __restrict__ B,
       int M, int N, int K, int lda, int ldb,
       const float* __restrict__ bias,
       const float* __restrict__ aux0,
       const float* __restrict__ aux1,
       const float* __restrict__ aux2,
       const float* __restrict__ fb2p,
       float* __restrict__ Cout, int ldo, int bsB, int bsC)
{
    __shared__ __align__(16) float As[2][KT][72];
    __shared__ __align__(16) float Bs[2][KT][72];

    const float* Ap = (EPI == 1) ? g_ex : (EPI == 2) ? g_h : (EPI == 3) ? g_mtd : A;
    B    += (size_t)blockIdx.z * bsB;
    Cout += (size_t)blockIdx.z * bsC;

    int tid = threadIdx.x;
    int tx = tid & 15, ty = tid >> 4;
    int m0 = blockIdx.y * 64, n0 = blockIdx.x * 64;

    int sr  = tid >> 2;          // 0..63 (row for A / BLAY0 B)
    int sc8 = (tid & 3) * 8;     // k-offset base
    int skk = tid >> 6;          // 0..3  (BLAY1)
    int snn = tid & 63;          // 0..63 (BLAY1)

    float ra[8], rb[8];

    #pragma unroll
    for (int u = 0; u < 8; u++) {
        int k = sc8 + u;
        ra[u] = (k < K) ? Ap[(m0 + sr) * lda + k] : 0.f;
    }
    if (BLAY == 0) {
        #pragma unroll
        for (int u = 0; u < 8; u++) {
            int k = sc8 + u;
            int n = n0 + sr;
            rb[u] = (k < K && n < N) ? B[n * ldb + k] : 0.f;
        }
    } else {
        #pragma unroll
        for (int u = 0; u < 8; u++) {
            int k = skk + u * 4;
            int n = n0 + snn;
            rb[u] = (k < K && n < N) ? B[k * ldb + n] : 0.f;
        }
    }
    #pragma unroll
    for (int u = 0; u < 8; u++) As[0][sc8 + u][sr] = ra[u];
    if (BLAY == 0) {
        #pragma unroll
        for (int u = 0; u < 8; u++) Bs[0][sc8 + u][sr] = rb[u];
    } else {
        #pragma unroll
        for (int u = 0; u < 8; u++) Bs[0][skk + u * 4][snn] = rb[u];
    }
    __syncthreads();

    u64 acc2[4][2] = {};
    int cur = 0;

    for (int k0 = 0; k0 < K; k0 += KT) {
        bool has_next = (k0 + KT < K);
        if (has_next) {
            int kb = k0 + KT;
            #pragma unroll
            for (int u = 0; u < 8; u++) {
                int k = kb + sc8 + u;
                ra[u] = (k < K) ? Ap[(m0 + sr) * lda + k] : 0.f;
            }
            if (BLAY == 0) {
                #pragma unroll
                for (int u = 0; u < 8; u++) {
                    int k = kb + sc8 + u;
                    int n = n0 + sr;
                    rb[u] = (k < K && n < N) ? B[n * ldb + k] : 0.f;
                }
            } else {
                #pragma unroll
                for (int u = 0; u < 8; u++) {
                    int k = kb + skk + u * 4;
                    int n = n0 + snn;
                    rb[u] = (k < K && n < N) ? B[k * ldb + n] : 0.f;
                }
            }
        }
        #pragma unroll
        for (int kk = 0; kk < KT; kk++) {
            float4 av = *(const float4*)&As[cur][kk][ty * 4];
            float4 bv = *(const float4*)&Bs[cur][kk][tx * 4];
            u64 b01 = pk2(bv.x, bv.y);
            u64 b23 = pk2(bv.z, bv.w);
            float a[4] = {av.x, av.y, av.z, av.w};
            #pragma unroll
            for (int i = 0; i < 4; i++) {
                u64 a2 = pk2(a[i], a[i]);
                acc2[i][0] = fma2(a2, b01, acc2[i][0]);
                acc2[i][1] = fma2(a2, b23, acc2[i][1]);
            }
        }
        if (has_next) {
            int nxt = cur ^ 1;
            #pragma unroll
            for (int u = 0; u < 8; u++) As[nxt][sc8 + u][sr] = ra[u];
            if (BLAY == 0) {
                #pragma unroll
                for (int u = 0; u < 8; u++) Bs[nxt][sc8 + u][sr] = rb[u];
            } else {
                #pragma unroll
                for (int u = 0; u < 8; u++) Bs[nxt][skk + u * 4][snn] = rb[u];
            }
            __syncthreads();
            cur = nxt;
        }
    }

    float acc[4][4];
    #pragma unroll
    for (int i = 0; i < 4; i++) {
        float2 p0 = upk2(acc2[i][0]);
        float2 p1 = upk2(acc2[i][1]);
        acc[i][0] = p0.x; acc[i][1] = p0.y;
        acc[i][2] = p1.x; acc[i][3] = p1.y;
    }

    #pragma unroll
    for (int i = 0; i < 4; i++) {
        int m = m0 + ty * 4 + i;
        if (m >= M) continue;
        #pragma unroll
        for (int j = 0; j < 4; j++) {
            int n = n0 + tx * 4 + j;
            if (n >= N) continue;
            float v = acc[i][j];
            if (EPI == 0) {
                int t = m & (NT - 1);
                float freq = expf(-(float)(n & ~1) * (9.210340371976184f / 512.0f));
                float ang = (float)t * freq;
                float pe = (n & 1) ? cosf(ang) : sinf(ang);
                g_ex[m * ND + n] = v + bias[n] + pe;
            } else if (EPI == 1) {
                g_h[m * ND + n] = gelu_f(v + bias[n]);
            } else if (EPI == 2) {
                float s = sigm_f(v + bias[n]);
                if (g_tmask[m]) s = aux0[n];          // t_token
                Cout[m * ldo + n] = s;
            } else if (EPI == 3) {
                float o = v;                           // mx value
                if (!g_tm[m]) {
                    float s = 0.f;
                    for (int d = 0; d < ND; d++) {
                        float hv = gelu_f(v * aux0[d] + aux1[d]);  // fW1, fb1
                        s += hv * aux2[d];                          // fW2
                    }
                    o = sigm_f(s + fb2p[0]);
                }
                Cout[m * ldo + n] = o;
            } else if (EPI == 4) {
                Cout[m * ldo + n] = v;
            } else {  // EPI == 5
                Cout[m * ldo + n] = v * (1.f / 512.f);
            }
        }
    }
}

// ---------------- windowed variance score (shuffle reduction) --------------
__global__ void score_k() {
    int t = blockIdx.x, b = blockIdx.y;
    int tid = threadIdx.x;                 // 256 threads, 2 d each
    int t0 = t - (WINW - 1); if (t0 < 0) t0 = 0;
    float den = (float)((t + 1 < WINW) ? (t + 1) : WINW);
    float vs = 0.f, ms = 0.f;
    #pragma unroll
    for (int h = 0; h < 2; h++) {
        int d = tid + h * 256;
        float s1 = 0.f, s2 = 0.f;
        for (int tt = t0; tt <= t; tt++) {
            float e = g_ex[(b * NT + tt) * ND + d];
            s1 += e; s2 += e * e;
        }
        float m1 = s1 / den;
        vs += s2 / den - m1 * m1;
        ms += m1;
    }
    __shared__ float pv[8], pm[8];
    #pragma unroll
    for (int o = 16; o; o >>= 1) {
        vs += __shfl_down_sync(0xffffffffu, vs, o);
        ms += __shfl_down_sync(0xffffffffu, ms, o);
    }
    if ((tid & 31) == 0) { pv[tid >> 5] = vs; pm[tid >> 5] = ms; }
    __syncthreads();
    if (tid < 32) {
        float v2 = (tid < 8) ? pv[tid] : 0.f;
        float m2 = (tid < 8) ? pm[tid] : 0.f;
        #pragma unroll
        for (int o = 4; o; o >>= 1) {
            v2 += __shfl_down_sync(0xffffffffu, v2, o);
            m2 += __shfl_down_sync(0xffffffffu, m2, o);
        }
        if (tid == 0) g_score[b * NT + t] = v2 / (m2 + 1e-6f);
    }
}

// ---------------- top-k via bitonic sort, both problems in one launch ------
__global__ void __launch_bounds__(512) topk_k(float* __restrict__ out) {
    int b = blockIdx.x, which = blockIdx.y;
    const float* vals = which ? g_magsum : g_score;
    int n = which ? NF : NT;
    int* idxo = which ? g_fidx : g_tidx;
    unsigned char* mask = which ? g_fmask : g_tmask;
    int mstride = which ? NF : NT;
    float* fout = out + (which ? FIDX_OFF : TIDX_OFF);

    __shared__ float sv[512];
    __shared__ int   si[512];
    int tid = threadIdx.x;
    const float NEGINF = -__int_as_float(0x7f800000);
    sv[tid] = (tid < n) ? vals[b * n + tid] : NEGINF;
    si[tid] = tid;
    __syncthreads();

    #pragma unroll 1
    for (int k = 2; k <= 512; k <<= 1) {
        #pragma unroll 1
        for (int j = k >> 1; j > 0; j >>= 1) {
            int ixj = tid ^ j;
            if (ixj > tid) {
                float v1 = sv[tid], v2 = sv[ixj];
                int   i1 = si[tid], i2 = si[ixj];
                bool lt = (v1 < v2) || (v1 == v2 && i1 > i2); // tid-elem "worse"
                bool up = ((tid & k) == 0);
                if (lt == up) {
                    sv[tid] = v2; sv[ixj] = v1;
                    si[tid] = i2; si[ixj] = i1;
                }
            }
            __syncthreads();
        }
    }
    if (tid < NK) {
        int idx = si[tid];
        idxo[b * NK + tid] = idx;
        fout[b * NK + tid] = (float)idx;
        mask[b * mstride + idx] = 1;
    }
}

// ---------------- deterministic magnitude reduction over D (shuffle) -------
__global__ void mag_k() {
    int f = blockIdx.x, b = blockIdx.y;
    int tid = threadIdx.x;                 // 256 threads, 2 d each
    float s = 0.f;
    #pragma unroll
    for (int h = 0; h < 2; h++) {
        int d = tid + h * 256;
        float re = g_c[b * CS + f * ND + d];
        float im = g_c[b * CS + (NF + f) * ND + d];
        s += sqrtf(re * re + im * im);
    }
    __shared__ float ps[8];
    #pragma unroll
    for (int o = 16; o; o >>= 1) s += __shfl_down_sync(0xffffffffu, s, o);
    if ((tid & 31) == 0) ps[tid >> 5] = s;
    __syncthreads();
    if (tid < 32) {
        float v = (tid < 8) ? ps[tid] : 0.f;
        #pragma unroll
        for (int o = 4; o; o >>= 1) v += __shfl_down_sync(0xffffffffu, v, o);
        if (tid == 0) g_magsum[b * NF + f] = v;
    }
}

// ---------------- time-domain mask of irfft(fmask) != 0 --------------------
__global__ void tm_k() {
    __shared__ double ctab[512];
    int b = blockIdx.x, t = threadIdx.x;
    ctab[t] = cospi((double)t / 256.0);
    __syncthreads();
    double v = 0.0;
    for (int i = 0; i < NK; i++) {
        int f = g_fidx[b * NK + i];
        double w = (f == 0 || f == 256) ? 1.0 : 2.0;
        v += w * ctab[(f * t) & 511];
    }
    g_tm[b * NT + t] = (v != 0.0) ? 1 : 0;
}

// ---------------- launch ----------------------------------------------------
// Launch order keeps the forward DFT-GEMM at index 3 (the profiled launch):
// fill_w(0), gemm_ex(1), score(2), gemm_dft(3), ...
extern "C" void kernel_launch(void* const* d_in, const int* in_sizes, int n_in,
                              void* d_out, int out_size) {
    const float* x       = (const float*)d_in[0];
    const float* W_emb   = (const float*)d_in[1];
    const float* b_emb   = (const float*)d_in[2];
    const float* t_token = (const float*)d_in[3];
    const float* tW1     = (const float*)d_in[4];
    const float* tb1     = (const float*)d_in[5];
    const float* tW2     = (const float*)d_in[6];
    const float* tb2     = (const float*)d_in[7];
    const float* f_re    = (const float*)d_in[8];
    const float* f_im    = (const float*)d_in[9];
    const float* fW1     = (const float*)d_in[10];
    const float* fb1     = (const float*)d_in[11];
    const float* fW2     = (const float*)d_in[12];
    const float* fb2     = (const float*)d_in[13];
    float* out = (float*)d_out;

    float* g_c_p;   cudaGetSymbolAddress((void**)&g_c_p,   g_c);
    float* g_cm_p;  cudaGetSymbolAddress((void**)&g_cm_p,  g_cm);
    float* g_wf_p;  cudaGetSymbolAddress((void**)&g_wf_p,  g_wf);
    float* g_wi_p;  cudaGetSymbolAddress((void**)&g_wi_p,  g_wi);
    float* g_ex_p;  cudaGetSymbolAddress((void**)&g_ex_p,  g_ex);
    float* g_mtd_p; cudaGetSymbolAddress((void**)&g_mtd_p, g_mtd);

    // idx 0: twiddles + mask init (fused)
    fill_w_k<<<MFP + NT, NT>>>();
    // idx 1: ex = x @ W_emb^T + b_emb + PE
    {
        dim3 g(ND / 64, (NB * NT) / 64);
        gemm_k<0, 0><<<g, 256>>>(x, W_emb, NB * NT, ND, NC, NC, NC,
                                 b_emb, nullptr, nullptr, nullptr, nullptr,
                                 nullptr, 0, 0, 0);
    }
    // idx 2: windowed variance score (needs only g_ex)
    {
        dim3 gs(NT, NB);
        score_k<<<gs, 256>>>();
    }
    // idx 3: forward DFT as GEMM  [re;im] = W_f @ ex  (z = batch)  <-- profiled
    {
        dim3 g(ND / 64, MFP / 64, NB);
        gemm_k<4, 1><<<g, 256>>>(g_wf_p, g_ex_p, MF, ND, NT, NT, ND,
                                 nullptr, nullptr, nullptr, nullptr, nullptr,
                                 g_c_p, ND, NT * ND, CS);
    }
    // idx 4-5: magnitudes, both topk problems
    {
        dim3 gm(NF, NB);
        mag_k<<<gm, 256>>>();
        topk_k<<<dim3(NB, 2), 512>>>(out);
    }
    // idx 6: masked+weighted spectrum (depends only on fmask + g_c)
    cmprep_k<<<dim3(MF, NB), ND>>>(f_re, f_im);
    // idx 7: inverse DFT as GEMM  mtd = (1/512) W_i @ cm  (z = batch)
    {
        dim3 g(ND / 64, NT / 64, NB);
        gemm_k<5, 1><<<g, 256>>>(g_wi_p, g_cm_p, NT, ND, MF, MF, ND,
                                 nullptr, nullptr, nullptr, nullptr, nullptr,
                                 g_mtd_p, ND, CS, NT * ND);
    }
    // idx 8: time-domain mask (needs fidx only)
    tm_k<<<NB, NT>>>();
    // idx 9: h = gelu(ex @ tW1^T + tb1)
    {
        dim3 g(ND / 64, (NB * NT) / 64);
        gemm_k<1, 0><<<g, 256>>>(nullptr, tW1, NB * NT, ND, ND, ND, ND,
                                 tb1, nullptr, nullptr, nullptr, nullptr,
                                 nullptr, 0, 0, 0);
        // idx 10: out_t = tmask ? t_token : sigmoid(h @ tW2^T + tb2)
        gemm_k<2, 0><<<g, 256>>>(nullptr, tW2, NB * NT, ND, ND, ND, ND,
                                 tb2, t_token, nullptr, nullptr, nullptr,
                                 out + OUT_T_OFF, ND, 0, 0);
    }
    // idx 11: out_f = tm ? (mtd @ W_emb) : scalarMLP(...)
    {
        dim3 g((NC + 63) / 64, (NB * NT) / 64);
        gemm_k<3, 1><<<g, 256>>>(nullptr, W_emb, NB * NT, NC, ND, ND, NC,
                                 nullptr, fW1, fb1, fW2, fb2,
                                 out + OUTF_OFF, NC, 0, 0);
    }
}

// round 16
// speedup vs baseline: 2.6660x; 1.0743x over previous
#include <cuda_runtime.h>
#include <math.h>

#define NB 2
#define NT 512
#define NC 263
#define ND 512
#define NF 257
#define NK 51
#define WINW 24

// output layout (concatenated, float32): out_t | tidx | out_f | fidx
#define OUT_T_OFF 0
#define TIDX_OFF  (NB*NT*ND)                 // 524288
#define OUTF_OFF  (TIDX_OFF + NB*NK)         // 524390
#define FIDX_OFF  (OUTF_OFF + NB*NT*NC)      // 793702

// DFT-as-GEMM dimensions
#define MF   (2*NF)          // 514 spectrum rows (re stacked over im)
#define MFP  576             // padded twiddle rows (multiple of 64)
#define CS   (MF*ND)         // per-batch spectrum stride

// ---------------- scratch (device globals; no allocation allowed) ----------
__device__ float g_ex [NB*NT*ND];
__device__ float g_h  [NB*NT*ND];
__device__ float g_mtd[NB*NT*ND];
__device__ float g_c  [NB*CS];
__device__ float g_cm [NB*CS];
__device__ float g_wf [MFP*NT];
__device__ float g_wi [NT*MF];
__device__ float g_score [NB*NT];
__device__ float g_magsum[NB*NF];
__device__ int   g_tidx[NB*NK];
__device__ int   g_fidx[NB*NK];
__device__ unsigned char g_tmask[NB*NT];
__device__ unsigned char g_fmask[NB*NF];
__device__ unsigned char g_tm   [NB*NT];

__device__ __forceinline__ float gelu_f(float x) {
    return 0.5f * x * (1.f + erff(x * 0.7071067811865476f));
}
__device__ __forceinline__ float sigm_f(float x) {
    return 1.f / (1.f + expf(-x));
}

// ---- packed f32x2 helpers (sm_103a; per-lane IEEE fp32 FMA) ---------------
typedef unsigned long long u64;
__device__ __forceinline__ u64 pk2(float lo, float hi) {
    u64 r; asm("mov.b64 %0, {%1, %2};" : "=l"(r) : "f"(lo), "f"(hi)); return r;
}
__device__ __forceinline__ float2 upk2(u64 v) {
    float2 r; asm("mov.b64 {%0, %1}, %2;" : "=f"(r.x), "=f"(r.y) : "l"(v)); return r;
}
__device__ __forceinline__ u64 fma2(u64 a, u64 b, u64 c) {
    u64 d; asm("fma.rn.f32x2 %0, %1, %2, %3;" : "=l"(d) : "l"(a), "l"(b), "l"(c)); return d;
}

// ---------------- fused twiddle fill + mask init ---------------------------
__global__ void fill_w_k() {
    int blk = blockIdx.x;
    if (blk == 0) {
        for (int j = threadIdx.x; j < NB*NF; j += blockDim.x) g_fmask[j] = 0;
    } else if (blk == 1) {
        for (int j = threadIdx.x; j < NB*NT; j += blockDim.x) g_tmask[j] = 0;
    }
    if (blk < MFP) {
        int r = blk, t = threadIdx.x;
        float v;
        if (r < NF)      v = cospif((float)((r * t) & 511) / 256.f);
        else if (r < MF) v = -sinpif((float)(((r - NF) * t) & 511) / 256.f);
        else             v = 0.f;
        g_wf[r * NT + t] = v;
    } else {
        int t = blk - MFP;
        for (int f = threadIdx.x; f < MF; f += blockDim.x) {
            float v;
            if (f < NF) v = cospif((float)((f * t) & 511) / 256.f);
            else        v = -sinpif((float)(((f - NF) * t) & 511) / 256.f);
            g_wi[t * MF + f] = v;
        }
    }
}

// ---------------- fused: masked spectrum prep + time-domain mask -----------
// blocks [0, MF) x NB: cmprep rows.  block MF (per batch): tm mask.
__global__ void cmtm_k(const float* __restrict__ tokre,
                       const float* __restrict__ tokim) {
    int r = blockIdx.x, b = blockIdx.y;
    if (r < MF) {
        int d = threadIdx.x;
        int f = (r < NF) ? r : (r - NF);
        float w = (f == 0 || f == 256) ? 1.f : 2.f;
        float v;
        if (g_fmask[b * NF + f]) v = (r < NF) ? tokre[d] : tokim[d];
        else                     v = g_c[b * CS + r * ND + d];
        g_cm[b * CS + r * ND + d] = w * v;
    } else {
        // time-domain mask of irfft(fmask) != 0 (double cospi table; exact)
        __shared__ double ctab[512];
        int t = threadIdx.x;
        ctab[t] = cospi((double)t / 256.0);
        __syncthreads();
        double v = 0.0;
        for (int i = 0; i < NK; i++) {
            int f = g_fidx[b * NK + i];
            double w = (f == 0 || f == 256) ? 1.0 : 2.0;
            v += w * ctab[(f * t) & 511];
        }
        g_tm[b * NT + t] = (v != 0.0) ? 1 : 0;
    }
}

// ---------------- runtime-dispatch batched/merged SGEMM --------------------
// 64x64 tile, KT=32, 256 threads, 4x4 thread tile, f32x2 FMA, double-buffered.
// Two independent GEMMs per launch (block-id split) to reach ~2 blocks/SM.
// epi: 0 ex(bias+PE) 1 gelu->g_h 2 out_t 3 out_f 4 store 5 store/512
// blay: 0 B[N][K], 1 B[K][N].
struct GemmArgs {
    const float* A; const float* B;
    int M, N, K, lda, ldb;
    const float* bias; const float* aux0; const float* aux1;
    const float* aux2; const float* fb2p;
    float* C; int ldo, bsB, bsC;
    int epi, blay;
    int gx, gy;
};

#define KT 32
__global__ void __launch_bounds__(256)
gemm2_k(GemmArgs a0, GemmArgs a1, int nblk0)
{
    __shared__ __align__(16) float As[2][KT][72];
    __shared__ __align__(16) float Bs[2][KT][72];

    GemmArgs g;
    int bid = blockIdx.x;
    if (bid < nblk0) { g = a0; } else { g = a1; bid -= nblk0; }
    int bx = bid % g.gx;
    int t2 = bid / g.gx;
    int by = t2 % g.gy;
    int bz = t2 / g.gy;

    const float* A = g.A;
    const float* B = g.B + (size_t)bz * g.bsB;
    float* Cout    = g.C + (size_t)bz * g.bsC;
    int M = g.M, N = g.N, K = g.K, lda = g.lda, ldb = g.ldb, ldo = g.ldo;
    int blay = g.blay;

    int tid = threadIdx.x;
    int tx = tid & 15, ty = tid >> 4;
    int m0 = by * 64, n0 = bx * 64;

    int sr  = tid >> 2;
    int sc8 = (tid & 3) * 8;
    int skk = tid >> 6;
    int snn = tid & 63;

    float ra[8], rb[8];

    #pragma unroll
    for (int u = 0; u < 8; u++) {
        int k = sc8 + u;
        ra[u] = (k < K) ? A[(m0 + sr) * lda + k] : 0.f;
    }
    if (blay == 0) {
        #pragma unroll
        for (int u = 0; u < 8; u++) {
            int k = sc8 + u;
            int n = n0 + sr;
            rb[u] = (k < K && n < N) ? B[n * ldb + k] : 0.f;
        }
    } else {
        #pragma unroll
        for (int u = 0; u < 8; u++) {
            int k = skk + u * 4;
            int n = n0 + snn;
            rb[u] = (k < K && n < N) ? B[k * ldb + n] : 0.f;
        }
    }
    #pragma unroll
    for (int u = 0; u < 8; u++) As[0][sc8 + u][sr] = ra[u];
    if (blay == 0) {
        #pragma unroll
        for (int u = 0; u < 8; u++) Bs[0][sc8 + u][sr] = rb[u];
    } else {
        #pragma unroll
        for (int u = 0; u < 8; u++) Bs[0][skk + u * 4][snn] = rb[u];
    }
    __syncthreads();

    u64 acc2[4][2] = {};
    int cur = 0;

    for (int k0 = 0; k0 < K; k0 += KT) {
        bool has_next = (k0 + KT < K);
        if (has_next) {
            int kb = k0 + KT;
            #pragma unroll
            for (int u = 0; u < 8; u++) {
                int k = kb + sc8 + u;
                ra[u] = (k < K) ? A[(m0 + sr) * lda + k] : 0.f;
            }
            if (blay == 0) {
                #pragma unroll
                for (int u = 0; u < 8; u++) {
                    int k = kb + sc8 + u;
                    int n = n0 + sr;
                    rb[u] = (k < K && n < N) ? B[n * ldb + k] : 0.f;
                }
            } else {
                #pragma unroll
                for (int u = 0; u < 8; u++) {
                    int k = kb + skk + u * 4;
                    int n = n0 + snn;
                    rb[u] = (k < K && n < N) ? B[k * ldb + n] : 0.f;
                }
            }
        }
        #pragma unroll
        for (int kk = 0; kk < KT; kk++) {
            float4 av = *(const float4*)&As[cur][kk][ty * 4];
            float4 bv = *(const float4*)&Bs[cur][kk][tx * 4];
            u64 b01 = pk2(bv.x, bv.y);
            u64 b23 = pk2(bv.z, bv.w);
            float a[4] = {av.x, av.y, av.z, av.w};
            #pragma unroll
            for (int i = 0; i < 4; i++) {
                u64 a2 = pk2(a[i], a[i]);
                acc2[i][0] = fma2(a2, b01, acc2[i][0]);
                acc2[i][1] = fma2(a2, b23, acc2[i][1]);
            }
        }
        if (has_next) {
            int nxt = cur ^ 1;
            #pragma unroll
            for (int u = 0; u < 8; u++) As[nxt][sc8 + u][sr] = ra[u];
            if (blay == 0) {
                #pragma unroll
                for (int u = 0; u < 8; u++) Bs[nxt][sc8 + u][sr] = rb[u];
            } else {
                #pragma unroll
                for (int u = 0; u < 8; u++) Bs[nxt][skk + u * 4][snn] = rb[u];
            }
            __syncthreads();
            cur = nxt;
        }
    }

    float acc[4][4];
    #pragma unroll
    for (int i = 0; i < 4; i++) {
        float2 p0 = upk2(acc2[i][0]);
        float2 p1 = upk2(acc2[i][1]);
        acc[i][0] = p0.x; acc[i][1] = p0.y;
        acc[i][2] = p1.x; acc[i][3] = p1.y;
    }

    int epi = g.epi;
    #pragma unroll
    for (int i = 0; i < 4; i++) {
        int m = m0 + ty * 4 + i;
        if (m >= M) continue;
        #pragma unroll
        for (int j = 0; j < 4; j++) {
            int n = n0 + tx * 4 + j;
            if (n >= N) continue;
            float v = acc[i][j];
            if (epi == 0) {
                int t = m & (NT - 1);
                float freq = expf(-(float)(n & ~1) * (9.210340371976184f / 512.0f));
                float ang = (float)t * freq;
                float pe = (n & 1) ? cosf(ang) : sinf(ang);
                g_ex[m * ND + n] = v + g.bias[n] + pe;
            } else if (epi == 1) {
                g_h[m * ND + n] = gelu_f(v + g.bias[n]);
            } else if (epi == 2) {
                float s = sigm_f(v + g.bias[n]);
                if (g_tmask[m]) s = g.aux0[n];        // t_token
                Cout[m * ldo + n] = s;
            } else if (epi == 3) {
                float o = v;                           // mx value
                if (!g_tm[m]) {
                    float s = 0.f;
                    for (int d = 0; d < ND; d++) {
                        float hv = gelu_f(v * g.aux0[d] + g.aux1[d]);
                        s += hv * g.aux2[d];
                    }
                    o = sigm_f(s + g.fb2p[0]);
                }
                Cout[m * ldo + n] = o;
            } else if (epi == 4) {
                Cout[m * ldo + n] = v;
            } else {  // epi == 5
                Cout[m * ldo + n] = v * (1.f / 512.f);
            }
        }
    }
}

// ---------------- windowed variance score (shuffle reduction) --------------
__global__ void score_k() {
    int t = blockIdx.x, b = blockIdx.y;
    int tid = threadIdx.x;
    int t0 = t - (WINW - 1); if (t0 < 0) t0 = 0;
    float den = (float)((t + 1 < WINW) ? (t + 1) : WINW);
    float vs = 0.f, ms = 0.f;
    #pragma unroll
    for (int h = 0; h < 2; h++) {
        int d = tid + h * 256;
        float s1 = 0.f, s2 = 0.f;
        for (int tt = t0; tt <= t; tt++) {
            float e = g_ex[(b * NT + tt) * ND + d];
            s1 += e; s2 += e * e;
        }
        float m1 = s1 / den;
        vs += s2 / den - m1 * m1;
        ms += m1;
    }
    __shared__ float pv[8], pm[8];
    #pragma unroll
    for (int o = 16; o; o >>= 1) {
        vs += __shfl_down_sync(0xffffffffu, vs, o);
        ms += __shfl_down_sync(0xffffffffu, ms, o);
    }
    if ((tid & 31) == 0) { pv[tid >> 5] = vs; pm[tid >> 5] = ms; }
    __syncthreads();
    if (tid < 32) {
        float v2 = (tid < 8) ? pv[tid] : 0.f;
        float m2 = (tid < 8) ? pm[tid] : 0.f;
        #pragma unroll
        for (int o = 4; o; o >>= 1) {
            v2 += __shfl_down_sync(0xffffffffu, v2, o);
            m2 += __shfl_down_sync(0xffffffffu, m2, o);
        }
        if (tid == 0) g_score[b * NT + t] = v2 / (m2 + 1e-6f);
    }
}

// ---------------- top-k via bitonic sort, both problems in one launch ------
__global__ void __launch_bounds__(512) topk_k(float* __restrict__ out) {
    int b = blockIdx.x, which = blockIdx.y;
    const float* vals = which ? g_magsum : g_score;
    int n = which ? NF : NT;
    int* idxo = which ? g_fidx : g_tidx;
    unsigned char* mask = which ? g_fmask : g_tmask;
    int mstride = which ? NF : NT;
    float* fout = out + (which ? FIDX_OFF : TIDX_OFF);

    __shared__ float sv[512];
    __shared__ int   si[512];
    int tid = threadIdx.x;
    const float NEGINF = -__int_as_float(0x7f800000);
    sv[tid] = (tid < n) ? vals[b * n + tid] : NEGINF;
    si[tid] = tid;
    __syncthreads();

    #pragma unroll 1
    for (int k = 2; k <= 512; k <<= 1) {
        #pragma unroll 1
        for (int j = k >> 1; j > 0; j >>= 1) {
            int ixj = tid ^ j;
            if (ixj > tid) {
                float v1 = sv[tid], v2 = sv[ixj];
                int   i1 = si[tid], i2 = si[ixj];
                bool lt = (v1 < v2) || (v1 == v2 && i1 > i2);
                bool up = ((tid & k) == 0);
                if (lt == up) {
                    sv[tid] = v2; sv[ixj] = v1;
                    si[tid] = i2; si[ixj] = i1;
                }
            }
            __syncthreads();
        }
    }
    if (tid < NK) {
        int idx = si[tid];
        idxo[b * NK + tid] = idx;
        fout[b * NK + tid] = (float)idx;
        mask[b * mstride + idx] = 1;
    }
}

// ---------------- deterministic magnitude reduction over D (shuffle) -------
__global__ void mag_k() {
    int f = blockIdx.x, b = blockIdx.y;
    int tid = threadIdx.x;
    float s = 0.f;
    #pragma unroll
    for (int h = 0; h < 2; h++) {
        int d = tid + h * 256;
        float re = g_c[b * CS + f * ND + d];
        float im = g_c[b * CS + (NF + f) * ND + d];
        s += sqrtf(re * re + im * im);
    }
    __shared__ float ps[8];
    #pragma unroll
    for (int o = 16; o; o >>= 1) s += __shfl_down_sync(0xffffffffu, s, o);
    if ((tid & 31) == 0) ps[tid >> 5] = s;
    __syncthreads();
    if (tid < 32) {
        float v = (tid < 8) ? ps[tid] : 0.f;
        #pragma unroll
        for (int o = 4; o; o >>= 1) v += __shfl_down_sync(0xffffffffu, v, o);
        if (tid == 0) g_magsum[b * NF + f] = v;
    }
}

// ---------------- launch ----------------------------------------------------
// Order: fill_w(0), ex(1), score(2), MERGED dft+h (3: profiled), mag(4),
// topk(5), MERGED cmprep+tm(6), MERGED idft+out_t(7), out_f(8).
extern "C" void kernel_launch(void* const* d_in, const int* in_sizes, int n_in,
                              void* d_out, int out_size) {
    const float* x       = (const float*)d_in[0];
    const float* W_emb   = (const float*)d_in[1];
    const float* b_emb   = (const float*)d_in[2];
    const float* t_token = (const float*)d_in[3];
    const float* tW1     = (const float*)d_in[4];
    const float* tb1     = (const float*)d_in[5];
    const float* tW2     = (const float*)d_in[6];
    const float* tb2     = (const float*)d_in[7];
    const float* f_re    = (const float*)d_in[8];
    const float* f_im    = (const float*)d_in[9];
    const float* fW1     = (const float*)d_in[10];
    const float* fb1     = (const float*)d_in[11];
    const float* fW2     = (const float*)d_in[12];
    const float* fb2     = (const float*)d_in[13];
    float* out = (float*)d_out;

    float* g_c_p;   cudaGetSymbolAddress((void**)&g_c_p,   g_c);
    float* g_cm_p;  cudaGetSymbolAddress((void**)&g_cm_p,  g_cm);
    float* g_wf_p;  cudaGetSymbolAddress((void**)&g_wf_p,  g_wf);
    float* g_wi_p;  cudaGetSymbolAddress((void**)&g_wi_p,  g_wi);
    float* g_ex_p;  cudaGetSymbolAddress((void**)&g_ex_p,  g_ex);
    float* g_h_p;   cudaGetSymbolAddress((void**)&g_h_p,   g_h);
    float* g_mtd_p; cudaGetSymbolAddress((void**)&g_mtd_p, g_mtd);

    GemmArgs Z = {};

    // idx 0: twiddles + mask init (fused)
    fill_w_k<<<MFP + NT, NT>>>();

    // idx 1: ex = x @ W_emb^T + b_emb + PE
    {
        GemmArgs a = Z;
        a.A = x; a.B = W_emb; a.M = NB*NT; a.N = ND; a.K = NC;
        a.lda = NC; a.ldb = NC; a.bias = b_emb;
        a.C = g_ex_p; a.ldo = ND; a.epi = 0; a.blay = 0;
        a.gx = ND/64; a.gy = (NB*NT)/64;
        int nb = a.gx * a.gy;
        gemm2_k<<<nb, 256>>>(a, a, nb);
    }
    // idx 2: windowed variance score
    {
        dim3 gs(NT, NB);
        score_k<<<gs, 256>>>();
    }
    // idx 3: MERGED forward DFT-GEMM + h-GEMM   <-- profiled
    {
        GemmArgs a = Z;   // dft: [re;im] = W_f @ ex (z batches)
        a.A = g_wf_p; a.B = g_ex_p; a.M = MF; a.N = ND; a.K = NT;
        a.lda = NT; a.ldb = ND; a.C = g_c_p; a.ldo = ND;
        a.bsB = NT*ND; a.bsC = CS; a.epi = 4; a.blay = 1;
        a.gx = ND/64; a.gy = MFP/64;                 // 8 x 9, z=2
        int nba = a.gx * a.gy * NB;

        GemmArgs b = Z;   // h = gelu(ex @ tW1^T + tb1)
        b.A = g_ex_p; b.B = tW1; b.M = NB*NT; b.N = ND; b.K = ND;
        b.lda = ND; b.ldb = ND; b.bias = tb1;
        b.C = g_h_p; b.ldo = ND; b.epi = 1; b.blay = 0;
        b.gx = ND/64; b.gy = (NB*NT)/64;             // 8 x 16
        int nbb = b.gx * b.gy;

        gemm2_k<<<nba + nbb, 256>>>(a, b, nba);
    }
    // idx 4-5: magnitudes, both topk problems
    {
        dim3 gm(NF, NB);
        mag_k<<<gm, 256>>>();
        topk_k<<<dim3(NB, 2), 512>>>(out);
    }
    // idx 6: MERGED masked+weighted spectrum + time-domain mask
    cmtm_k<<<dim3(MF + 1, NB), ND>>>(f_re, f_im);
    // idx 7: MERGED inverse DFT-GEMM + out_t-GEMM
    {
        GemmArgs a = Z;   // mtd = (1/512) W_i @ cm (z batches)
        a.A = g_wi_p; a.B = g_cm_p; a.M = NT; a.N = ND; a.K = MF;
        a.lda = MF; a.ldb = ND; a.C = g_mtd_p; a.ldo = ND;
        a.bsB = CS; a.bsC = NT*ND; a.epi = 5; a.blay = 1;
        a.gx = ND/64; a.gy = NT/64;                  // 8 x 8, z=2
        int nba = a.gx * a.gy * NB;

        GemmArgs b = Z;   // out_t = tmask? token : sigmoid(h @ tW2^T + tb2)
        b.A = g_h_p; b.B = tW2; b.M = NB*NT; b.N = ND; b.K = ND;
        b.lda = ND; b.ldb = ND; b.bias = tb2; b.aux0 = t_token;
        b.C = out + OUT_T_OFF; b.ldo = ND; b.epi = 2; b.blay = 0;
        b.gx = ND/64; b.gy = (NB*NT)/64;             // 8 x 16
        int nbb = b.gx * b.gy;

        gemm2_k<<<nba + nbb, 256>>>(a, b, nba);
    }
    // idx 8: out_f = tm ? (mtd @ W_emb) : scalarMLP(...)
    {
        GemmArgs a = Z;
        a.A = g_mtd_p; a.B = W_emb; a.M = NB*NT; a.N = NC; a.K = ND;
        a.lda = ND; a.ldb = NC;
        a.aux0 = fW1; a.aux1 = fb1; a.aux2 = fW2; a.fb2p = fb2;
        a.C = out + OUTF_OFF; a.ldo = NC; a.epi = 3; a.blay = 1;
        a.gx = (NC + 63)/64; a.gy = (NB*NT)/64;      // 5 x 16
        int nb = a.gx * a.gy;
        gemm2_k<<<nb, 256>>>(a, a, nb);
    }
}